// round 2
// baseline (speedup 1.0000x reference)
#include <cuda_runtime.h>
#include <math.h>

// ---------------- problem constants ----------------
#define BSZ   8
#define MSEQ  1024
#define HDIM  1024
#define NHEAD 16
#define HDHD  64
#define HU    256
#define TOK   (BSZ*MSEQ)          // 8192

// ---------------- scratch (__device__ globals: allowed, no runtime alloc) ----
__device__ float g_Q[TOK*HDIM];
__device__ float g_K[TOK*HDIM];
__device__ float g_V[TOK*HDIM];
__device__ float g_G[TOK*HDIM];
__device__ float g_H[TOK*HU];
__device__ float g_sigma[TOK];
__device__ float g_ctxp[BSZ*NHEAD*32*HDHD];   // per-(b,h,mtile) partial sums of ctx*g

// =====================================================================
// Kernel 1: tiled SGEMM  out = act(x @ W + bias)
//   blockIdx.z: 0=Q 1=K 2=V 3=G(sigmoid) 4=U1(relu, N=256)
// 128x128 tile, BK=16, 256 threads, 8x8 microtile
// =====================================================================
__global__ __launch_bounds__(256, 2)
void gemm_kernel(const float* __restrict__ x,
                 const float* __restrict__ Wq, const float* __restrict__ bq,
                 const float* __restrict__ Wk, const float* __restrict__ bk,
                 const float* __restrict__ Wv, const float* __restrict__ bv,
                 const float* __restrict__ Wg, const float* __restrict__ bg,
                 const float* __restrict__ Wu1, const float* __restrict__ bu1)
{
    int which = blockIdx.z;
    const float* W; const float* bias; float* out; int N;
    switch (which) {
        case 0: W = Wq;  bias = bq;  out = g_Q; N = 1024; break;
        case 1: W = Wk;  bias = bk;  out = g_K; N = 1024; break;
        case 2: W = Wv;  bias = bv;  out = g_V; N = 1024; break;
        case 3: W = Wg;  bias = bg;  out = g_G; N = 1024; break;
        default:W = Wu1; bias = bu1; out = g_H; N = 256;  break;
    }
    int n0 = blockIdx.x * 128;
    if (n0 >= N) return;
    int m0 = blockIdx.y * 128;

    __shared__ float As[16][128];   // transposed: As[k][m]
    __shared__ float Bs[16][128];   // Bs[k][n]

    int t  = threadIdx.x;
    int ty = t >> 4, tx = t & 15;

    float acc[8][8];
    #pragma unroll
    for (int i = 0; i < 8; i++)
        #pragma unroll
        for (int j = 0; j < 8; j++) acc[i][j] = 0.0f;

    int arow = t >> 2;            // 0..63 (also +64)
    int acol = (t & 3) << 2;      // 0,4,8,12
    int brow = t >> 4;            // 0..15
    int bcol = (t & 15) << 3;     // 0..120

    for (int k0 = 0; k0 < 1024; k0 += 16) {
        float4 a0 = *(const float4*)(x + (size_t)(m0 + arow     ) * 1024 + k0 + acol);
        float4 a1 = *(const float4*)(x + (size_t)(m0 + arow + 64) * 1024 + k0 + acol);
        float4 b0 = *(const float4*)(W + (size_t)(k0 + brow) * N + n0 + bcol);
        float4 b1 = *(const float4*)(W + (size_t)(k0 + brow) * N + n0 + bcol + 4);
        __syncthreads();
        As[acol + 0][arow] = a0.x; As[acol + 1][arow] = a0.y;
        As[acol + 2][arow] = a0.z; As[acol + 3][arow] = a0.w;
        As[acol + 0][arow + 64] = a1.x; As[acol + 1][arow + 64] = a1.y;
        As[acol + 2][arow + 64] = a1.z; As[acol + 3][arow + 64] = a1.w;
        *(float4*)&Bs[brow][bcol]     = b0;
        *(float4*)&Bs[brow][bcol + 4] = b1;
        __syncthreads();
        #pragma unroll
        for (int k = 0; k < 16; k++) {
            float4 av0 = *(const float4*)&As[k][ty * 8];
            float4 av1 = *(const float4*)&As[k][ty * 8 + 4];
            float4 bv0 = *(const float4*)&Bs[k][tx * 8];
            float4 bv1 = *(const float4*)&Bs[k][tx * 8 + 4];
            float am[8] = {av0.x, av0.y, av0.z, av0.w, av1.x, av1.y, av1.z, av1.w};
            float bn[8] = {bv0.x, bv0.y, bv0.z, bv0.w, bv1.x, bv1.y, bv1.z, bv1.w};
            #pragma unroll
            for (int i = 0; i < 8; i++)
                #pragma unroll
                for (int j = 0; j < 8; j++)
                    acc[i][j] = fmaf(am[i], bn[j], acc[i][j]);
        }
    }

    #pragma unroll
    for (int i = 0; i < 8; i++) {
        int row = m0 + ty * 8 + i;
        #pragma unroll
        for (int j = 0; j < 8; j++) {
            int col = n0 + tx * 8 + j;
            float v = acc[i][j] + bias[col];
            if (which == 3)       v = 1.0f / (1.0f + expf(-v));   // sigmoid gate
            else if (which == 4)  v = fmaxf(v, 0.0f);             // relu
            acc[i][j] = v;
        }
        *(float4*)(out + (size_t)row * N + n0 + tx * 8)     =
            make_float4(acc[i][0], acc[i][1], acc[i][2], acc[i][3]);
        *(float4*)(out + (size_t)row * N + n0 + tx * 8 + 4) =
            make_float4(acc[i][4], acc[i][5], acc[i][6], acc[i][7]);
    }
}

// =====================================================================
// Kernel 2: sigma = softplus(H @ Wu2 + bu2) + 1e-6  (H already relu'd)
// one warp per row
// =====================================================================
__global__ void sigma_finish_kernel(const float* __restrict__ Wu2,
                                    const float* __restrict__ bu2,
                                    float* __restrict__ out_sigma)
{
    int w = threadIdx.x >> 5, lane = threadIdx.x & 31;
    int row = blockIdx.x * 8 + w;
    const float* hr = g_H + (size_t)row * HU;
    float s = 0.0f;
    #pragma unroll
    for (int c = 0; c < 8; c++) {
        int j = lane + (c << 5);
        s = fmaf(hr[j], Wu2[j], s);
    }
    #pragma unroll
    for (int o = 16; o > 0; o >>= 1) s += __shfl_xor_sync(0xffffffffu, s, o);
    if (lane == 0) {
        float u  = s + bu2[0];
        float sp = fmaxf(u, 0.0f) + log1pf(expf(-fabsf(u))) + 1e-6f;
        g_sigma[row]   = sp;
        out_sigma[row] = sp;
    }
}

// =====================================================================
// Kernel 3: attention. Block = (mtile 32 rows, head, batch). 256 threads.
// Full score rows (32x1024 fp32) live in smem -> exact softmax, write attn,
// then P@V, gate with g, reduce rows into g_ctxp.
// =====================================================================
#define ATTN_SMEM_FLOATS (32*1024 + 64*32 + 128*65 + 1024 + 256)

__global__ __launch_bounds__(256, 1)
void attn_kernel(float* __restrict__ attn_out)
{
    extern __shared__ float sm[];
    float* S   = sm;                  // [32][1024] scores -> probs
    float* Qs  = S  + 32 * 1024;      // [k][m] 64x32
    float* KVs = Qs + 64 * 32;        // K: [k][128] (8192) | V: [n][65] (8320)
    float* rs  = KVs + 128 * 65;      // 1/sigma, 1024
    float* red = rs + 1024;           // [4][64]

    int mt = blockIdx.x, h = blockIdx.y, b = blockIdx.z;
    int m0 = mt * 32;
    int t  = threadIdx.x;

    for (int i = t; i < 1024; i += 256) rs[i] = 1.0f / g_sigma[b * 1024 + i];

    {   // load Q tile transposed: Qs[k][m]
        int m = t >> 3, part = t & 7;
        const float* qp = g_Q + ((size_t)(b * 1024 + m0 + m)) * 1024 + h * 64 + part * 8;
        float4 q0 = *(const float4*)qp;
        float4 q1 = *(const float4*)(qp + 4);
        int k = part * 8;
        Qs[(k+0)*32+m]=q0.x; Qs[(k+1)*32+m]=q0.y; Qs[(k+2)*32+m]=q0.z; Qs[(k+3)*32+m]=q0.w;
        Qs[(k+4)*32+m]=q1.x; Qs[(k+5)*32+m]=q1.y; Qs[(k+6)*32+m]=q1.z; Qs[(k+7)*32+m]=q1.w;
    }
    __syncthreads();

    // ---- scores: S[m][n] = (Q·K)/8 / (sigma_m * sigma_n) ----
    int tmS = (t >> 5) << 2;   // 0..28
    int tnS = (t & 31) << 2;   // 0..124
    for (int nt = 0; nt < 8; nt++) {
        int n0 = nt << 7;
        {   // load K tile transposed: KVs[k][n], k-stride 128
            int n = t >> 1, part = t & 1;
            const float* kp = g_K + ((size_t)(b * 1024 + n0 + n)) * 1024 + h * 64 + part * 32;
            #pragma unroll
            for (int i = 0; i < 8; i++) {
                float4 kv = *(const float4*)(kp + i * 4);
                int kk = part * 32 + i * 4;
                KVs[(kk+0)*128+n]=kv.x; KVs[(kk+1)*128+n]=kv.y;
                KVs[(kk+2)*128+n]=kv.z; KVs[(kk+3)*128+n]=kv.w;
            }
        }
        __syncthreads();
        float acc[4][4];
        #pragma unroll
        for (int i = 0; i < 4; i++)
            #pragma unroll
            for (int j = 0; j < 4; j++) acc[i][j] = 0.0f;
        #pragma unroll 16
        for (int k = 0; k < 64; k++) {
            float4 av = *(const float4*)&Qs[k * 32 + tmS];
            float4 bv = *(const float4*)&KVs[k * 128 + tnS];
            float am[4] = {av.x, av.y, av.z, av.w};
            float bn[4] = {bv.x, bv.y, bv.z, bv.w};
            #pragma unroll
            for (int i = 0; i < 4; i++)
                #pragma unroll
                for (int j = 0; j < 4; j++)
                    acc[i][j] = fmaf(am[i], bn[j], acc[i][j]);
        }
        #pragma unroll
        for (int i = 0; i < 4; i++) {
            int m = tmS + i;
            float fm = 0.125f * rs[m0 + m];
            #pragma unroll
            for (int j = 0; j < 4; j++) {
                int n = tnS + j;
                S[m * 1024 + n0 + n] = acc[i][j] * fm * rs[n0 + n];
            }
        }
        __syncthreads();
    }

    // ---- softmax per row; write attn; keep P in S ----
    {
        int w = t >> 5, lane = t & 31;
        float* ab = attn_out + ((size_t)((b * NHEAD + h) * 1024 + m0)) * 1024;
        for (int r = 0; r < 4; r++) {
            int m = (w << 2) + r;
            float* Sr = S + m * 1024;
            float mx = -1e30f;
            #pragma unroll
            for (int c = 0; c < 32; c++) mx = fmaxf(mx, Sr[lane + (c << 5)]);
            #pragma unroll
            for (int o = 16; o > 0; o >>= 1) mx = fmaxf(mx, __shfl_xor_sync(0xffffffffu, mx, o));
            float vals[32];
            float sum = 0.0f;
            #pragma unroll
            for (int c = 0; c < 32; c++) {
                float e = exp2f((Sr[lane + (c << 5)] - mx) * 1.4426950408889634f);
                vals[c] = e; sum += e;
            }
            #pragma unroll
            for (int o = 16; o > 0; o >>= 1) sum += __shfl_xor_sync(0xffffffffu, sum, o);
            float inv = 1.0f / sum;
            float* gr = ab + (size_t)m * 1024;
            #pragma unroll
            for (int c = 0; c < 32; c++) {
                float p = vals[c] * inv;
                Sr[lane + (c << 5)] = p;
                gr[lane + (c << 5)] = p;
            }
        }
    }
    __syncthreads();

    // ---- ctx = P @ V, gate, reduce over m ----
    int d = t & 63, mg = t >> 6;
    float acc8[8];
    #pragma unroll
    for (int i = 0; i < 8; i++) acc8[i] = 0.0f;

    for (int nt = 0; nt < 8; nt++) {
        int n0 = nt << 7;
        {   // V tile: KVs[n*65 + d] (pad 65 -> conflict-free)
            int n = t & 127, half = t >> 7;
            const float* vp = g_V + ((size_t)(b * 1024 + n0 + n)) * 1024 + h * 64 + half * 32;
            float* dst = KVs + n * 65 + half * 32;
            #pragma unroll
            for (int i = 0; i < 8; i++) {
                float4 vv = *(const float4*)(vp + i * 4);
                dst[i*4+0]=vv.x; dst[i*4+1]=vv.y; dst[i*4+2]=vv.z; dst[i*4+3]=vv.w;
            }
        }
        __syncthreads();
        #pragma unroll 4
        for (int n = 0; n < 128; n += 4) {
            float v0 = KVs[(n+0)*65 + d];
            float v1 = KVs[(n+1)*65 + d];
            float v2 = KVs[(n+2)*65 + d];
            float v3 = KVs[(n+3)*65 + d];
            #pragma unroll
            for (int i = 0; i < 8; i++) {
                float4 s4 = *(const float4*)&S[(mg * 8 + i) * 1024 + n0 + n];
                acc8[i] = fmaf(s4.x, v0, acc8[i]);
                acc8[i] = fmaf(s4.y, v1, acc8[i]);
                acc8[i] = fmaf(s4.z, v2, acc8[i]);
                acc8[i] = fmaf(s4.w, v3, acc8[i]);
            }
        }
        __syncthreads();
    }

    float part = 0.0f;
    #pragma unroll
    for (int i = 0; i < 8; i++) {
        int m = (mg << 3) + i;
        float gv = g_G[((size_t)(b * 1024 + m0 + m)) * 1024 + h * 64 + d];
        part = fmaf(acc8[i], gv, part);
    }
    red[(mg << 6) + d] = part;
    __syncthreads();
    if (t < 64) {
        float s = red[t] + red[64 + t] + red[128 + t] + red[192 + t];
        g_ctxp[(((size_t)(b * NHEAD + h)) * 32 + mt) * 64 + t] = s;
    }
}

// =====================================================================
// Kernel 4: z = mean_m(fused) @ Wo + bo
// =====================================================================
__global__ void z_kernel(const float* __restrict__ Wo, const float* __restrict__ bo,
                         float* __restrict__ z)
{
    __shared__ float mf[1024];
    int b = blockIdx.x;
    int t = threadIdx.x;   // 1024 threads: j = t = h*64+d
    const float* p = g_ctxp + ((size_t)(b * NHEAD + (t >> 6))) * 32 * 64 + (t & 63);
    float s = 0.0f;
    #pragma unroll
    for (int mt = 0; mt < 32; mt++) s += p[mt * 64];
    mf[t] = s * (1.0f / 1024.0f);
    __syncthreads();
    float acc = bo[t];
    for (int j = 0; j < 1024; j++) acc = fmaf(mf[j], Wo[j * 1024 + t], acc);
    z[(size_t)b * 1024 + t] = acc;
}

// =====================================================================
// launch
// =====================================================================
extern "C" void kernel_launch(void* const* d_in, const int* in_sizes, int n_in,
                              void* d_out, int out_size)
{
    const float* x   = (const float*)d_in[0];
    const float* Wq  = (const float*)d_in[1];  const float* bq  = (const float*)d_in[2];
    const float* Wk  = (const float*)d_in[3];  const float* bk  = (const float*)d_in[4];
    const float* Wv  = (const float*)d_in[5];  const float* bv  = (const float*)d_in[6];
    const float* Wg  = (const float*)d_in[7];  const float* bg  = (const float*)d_in[8];
    const float* Wo  = (const float*)d_in[9];  const float* bo  = (const float*)d_in[10];
    const float* Wu1 = (const float*)d_in[11]; const float* bu1 = (const float*)d_in[12];
    const float* Wu2 = (const float*)d_in[13]; const float* bu2 = (const float*)d_in[14];

    float* out       = (float*)d_out;
    float* z_out     = out;                                        // [8,1024]
    float* attn_out  = out + 8192;                                 // [8,16,1024,1024]
    float* sigma_out = out + 8192 + (size_t)BSZ*NHEAD*MSEQ*MSEQ;   // [8,1024]

    cudaFuncSetAttribute(attn_kernel, cudaFuncAttributeMaxDynamicSharedMemorySize,
                         ATTN_SMEM_FLOATS * (int)sizeof(float));

    // Q,K,V,G projections + U1 hidden layer
    gemm_kernel<<<dim3(8, 64, 5), 256>>>(x, Wq, bq, Wk, bk, Wv, bv, Wg, bg, Wu1, bu1);
    // sigma
    sigma_finish_kernel<<<TOK / 8, 256>>>(Wu2, bu2, sigma_out);
    // attention + gated ctx partials + attn output
    attn_kernel<<<dim3(32, NHEAD, BSZ), 256, ATTN_SMEM_FLOATS * (int)sizeof(float)>>>(attn_out);
    // pooled output
    z_kernel<<<BSZ, 1024>>>(Wo, bo, z_out);
}